// round 4
// baseline (speedup 1.0000x reference)
#include <cuda_runtime.h>
#include <cstdint>
#include <cstddef>

// ---------------------------------------------------------------------------
// RGAT layer: h[r] = x @ W[r]; per-edge attention with per-relation softmax;
// scatter-add weighted source features into destination nodes.
//
// Fixed problem shape (from reference setup_inputs):
//   x:          [50000, 128] f32
//   W:          [8, 128, 128] f32
//   edge_index: [2, 600000] int32  (JAX x64 disabled downgrades int64->int32!)
//   edge_type:  [600000] int32
//   out:        [50000, 128] f32
// ---------------------------------------------------------------------------

#define N_NODES 50000
#define N_EDGES 600000
#define DIM     128
#define N_REL   8

// Scratch (allocation-free rule: __device__ globals)
__device__ float    g_h[(size_t)N_REL * N_NODES * DIM];   // 204.8 MB
__device__ float    g_attn[N_EDGES];                      // attn, then exp(attn-max) in place
__device__ unsigned g_relmax[N_REL];                      // ordered-uint encoded max per relation
__device__ float    g_relsum[N_REL];                      // softmax denominators

// ---- helpers --------------------------------------------------------------

// Monotonic float<->uint mapping so atomicMax(unsigned) implements float max.
__device__ __forceinline__ unsigned f2ord(float f) {
    unsigned b = __float_as_uint(f);
    return (b & 0x80000000u) ? ~b : (b | 0x80000000u);
}
__device__ __forceinline__ float ord2f(unsigned u) {
    return (u & 0x80000000u) ? __uint_as_float(u & 0x7fffffffu)
                             : __uint_as_float(~u);
}

// Packed fp32x2 FMA (Blackwell): d = a*b + d on two lanes per register pair.
__device__ __forceinline__ void fma2(unsigned long long& d,
                                     unsigned long long a,
                                     unsigned long long b) {
    asm("fma.rn.f32x2 %0, %1, %2, %0;" : "+l"(d) : "l"(a), "l"(b));
}
__device__ __forceinline__ unsigned long long pk_dup(float x) {
    unsigned long long r;
    asm("mov.b64 %0, {%1, %1};" : "=l"(r) : "f"(x));
    return r;
}
__device__ __forceinline__ float2 unpk(unsigned long long v) {
    float2 f;
    asm("mov.b64 {%0, %1}, %2;" : "=f"(f.x), "=f"(f.y) : "l"(v));
    return f;
}

// ---- kernel 0: zero output, init reduction slots --------------------------

__global__ void init_kernel(float4* __restrict__ out) {
    int n = N_NODES * DIM / 4;
    float4 z = make_float4(0.f, 0.f, 0.f, 0.f);
    for (int i = blockIdx.x * blockDim.x + threadIdx.x; i < n;
         i += gridDim.x * blockDim.x)
        out[i] = z;
    if (blockIdx.x == 0 && threadIdx.x < N_REL) {
        g_relmax[threadIdx.x] = 0u;     // unsigned-min == identity for ord-max
        g_relsum[threadIdx.x] = 0.f;
    }
}

// ---- kernel 1: h[r] = x @ W[r], fp32 via packed f32x2 FMA ------------------
// Block: 128 rows of x, all 128 output cols, one relation (blockIdx.y).
// smem: x tile transposed xs[k][row] (pad 4 for 16B-aligned float4 row reads),
//       W[r] as ws[k][col].

#define BM   128
#define XST  132   // padded row stride (floats); 132*4=528 bytes, 16B aligned
#define GEMM_SMEM_BYTES ((DIM * XST + DIM * DIM) * 4)

__global__ void __launch_bounds__(256, 1)
gemm_kernel(const float* __restrict__ x, const float* __restrict__ W) {
    extern __shared__ float sm[];
    float* xs = sm;              // [DIM][XST] : xs[k*XST + row]
    float* ws = sm + DIM * XST;  // [DIM][DIM] : ws[k*DIM + col]

    const int r    = blockIdx.y;
    const int row0 = blockIdx.x * BM;
    const int tid  = threadIdx.x;

    // Load W[r] (coalesced, conflict-free store)
    {
        const float4* Wv = (const float4*)(W + (size_t)r * DIM * DIM);
        float4* wsv = (float4*)ws;
        #pragma unroll
        for (int i = tid; i < DIM * DIM / 4; i += 256) wsv[i] = Wv[i];
    }
    // Load x tile transposed: consecutive threads -> consecutive rows
    for (int i = tid; i < BM * (DIM / 4); i += 256) {
        int row = i & (BM - 1);
        int k4  = i >> 7;   // i / BM
        int gr  = row0 + row;
        float4 v = (gr < N_NODES)
                 ? *(const float4*)(x + (size_t)gr * DIM + k4 * 4)
                 : make_float4(0.f, 0.f, 0.f, 0.f);
        xs[(k4 * 4 + 0) * XST + row] = v.x;
        xs[(k4 * 4 + 1) * XST + row] = v.y;
        xs[(k4 * 4 + 2) * XST + row] = v.z;
        xs[(k4 * 4 + 3) * XST + row] = v.w;
    }
    __syncthreads();

    const int ty = tid >> 4;   // 0..15 -> rows ty*8 .. ty*8+7
    const int tx = tid & 15;   // 0..15 -> cols tx*8 .. tx*8+7 (4 col-pairs)

    unsigned long long acc[8][4];
    #pragma unroll
    for (int i = 0; i < 8; i++)
        #pragma unroll
        for (int j = 0; j < 4; j++) acc[i][j] = 0ULL;

    const float* xrow = xs + ty * 8;
    const float* wcol = ws + tx * 8;

    #pragma unroll 4
    for (int k = 0; k < DIM; k++) {
        float4 a0 = *(const float4*)(xrow + k * XST);
        float4 a1 = *(const float4*)(xrow + k * XST + 4);
        ulonglong2 b0 = *(const ulonglong2*)(wcol + k * DIM);
        ulonglong2 b1 = *(const ulonglong2*)(wcol + k * DIM + 4);
        float av[8] = {a0.x, a0.y, a0.z, a0.w, a1.x, a1.y, a1.z, a1.w};
        #pragma unroll
        for (int i = 0; i < 8; i++) {
            unsigned long long ad = pk_dup(av[i]);
            fma2(acc[i][0], ad, b0.x);
            fma2(acc[i][1], ad, b0.y);
            fma2(acc[i][2], ad, b1.x);
            fma2(acc[i][3], ad, b1.y);
        }
    }

    float* hb = g_h + (size_t)r * N_NODES * DIM;
    #pragma unroll
    for (int i = 0; i < 8; i++) {
        int gr = row0 + ty * 8 + i;
        if (gr < N_NODES) {
            float2 p0 = unpk(acc[i][0]), p1 = unpk(acc[i][1]);
            float2 p2 = unpk(acc[i][2]), p3 = unpk(acc[i][3]);
            float4 o0 = make_float4(p0.x, p0.y, p1.x, p1.y);
            float4 o1 = make_float4(p2.x, p2.y, p3.x, p3.y);
            *(float4*)(hb + (size_t)gr * DIM + tx * 8)     = o0;
            *(float4*)(hb + (size_t)gr * DIM + tx * 8 + 4) = o1;
        }
    }
}

// ---- kernel 2: per-edge attention + per-relation max -----------------------
// One warp per edge; 128-float rows -> one float4 per lane.

__global__ void attn_kernel(const int* __restrict__ ei,
                            const int* __restrict__ et) {
    __shared__ unsigned smax[N_REL];
    const int tid = threadIdx.x;
    if (tid < N_REL) smax[tid] = 0u;
    __syncthreads();

    const int lane = tid & 31;
    const int gw   = (blockIdx.x * blockDim.x + tid) >> 5;
    const int nw   = (gridDim.x * blockDim.x) >> 5;

    for (int e = gw; e < N_EDGES; e += nw) {
        int t = et[e];
        int s = ei[e];
        int d = ei[N_EDGES + e];
        const float4* hs = (const float4*)(g_h + ((size_t)t * N_NODES + s) * DIM);
        const float4* hd = (const float4*)(g_h + ((size_t)t * N_NODES + d) * DIM);
        float4 a = hs[lane];
        float4 b = hd[lane];
        float v = a.x * b.x + a.y * b.y + a.z * b.z + a.w * b.w;
        v += __shfl_xor_sync(0xffffffffu, v, 16);
        v += __shfl_xor_sync(0xffffffffu, v, 8);
        v += __shfl_xor_sync(0xffffffffu, v, 4);
        v += __shfl_xor_sync(0xffffffffu, v, 2);
        v += __shfl_xor_sync(0xffffffffu, v, 1);
        if (lane == 0) {
            v = (v > 0.f) ? v : 0.2f * v;   // leaky_relu, slope 0.2
            g_attn[e] = v;
            atomicMax(&smax[t], f2ord(v));
        }
    }
    __syncthreads();
    if (tid < N_REL) atomicMax(&g_relmax[tid], smax[tid]);
}

// ---- kernel 3: exp(attn - max[rel]) in place + per-relation sum ------------

__global__ void softmax_kernel(const int* __restrict__ et) {
    __shared__ float ssum[N_REL];
    __shared__ float smx[N_REL];
    const int tid = threadIdx.x;
    if (tid < N_REL) {
        ssum[tid] = 0.f;
        smx[tid]  = ord2f(g_relmax[tid]);
    }
    __syncthreads();

    const int stride = gridDim.x * blockDim.x;
    for (int e = blockIdx.x * blockDim.x + tid; e < N_EDGES; e += stride) {
        int t = et[e];
        float ex = expf(g_attn[e] - smx[t]);
        g_attn[e] = ex;
        atomicAdd(&ssum[t], ex);
    }
    __syncthreads();
    if (tid < N_REL) atomicAdd(&g_relsum[tid], ssum[tid]);
}

// ---- kernel 4: scatter out[dst] += a_e * h_src -----------------------------
// One warp per edge; each lane reduces a 16B chunk with one red.global.add.v4
// (4x fewer RED ops than scalar atomicAdd -> off the REDG issue-rate wall).

__global__ void scatter_kernel(const int* __restrict__ ei,
                               const int* __restrict__ et,
                               float* __restrict__ out) {
    const int tid  = threadIdx.x;
    const int lane = tid & 31;
    const int gw   = (blockIdx.x * blockDim.x + tid) >> 5;
    const int nw   = (gridDim.x * blockDim.x) >> 5;

    for (int e = gw; e < N_EDGES; e += nw) {
        int t = et[e];
        int s = ei[e];
        int d = ei[N_EDGES + e];
        float a = g_attn[e] / g_relsum[t];
        const float4* hs = (const float4*)(g_h + ((size_t)t * N_NODES + s) * DIM);
        float4 v = hs[lane];
        float* o = out + (size_t)d * DIM + lane * 4;   // 16B aligned
        asm volatile("red.global.add.v4.f32 [%0], {%1, %2, %3, %4};"
                     :: "l"(o), "f"(v.x * a), "f"(v.y * a),
                        "f"(v.z * a), "f"(v.w * a)
                     : "memory");
    }
}

// ---- launch ----------------------------------------------------------------

extern "C" void kernel_launch(void* const* d_in, const int* in_sizes, int n_in,
                              void* d_out, int out_size) {
    const float* x  = (const float*)d_in[0];
    const float* W  = (const float*)d_in[1];
    const int*   ei = (const int*)d_in[2];
    const int*   et = (const int*)d_in[3];
    float* out = (float*)d_out;

    init_kernel<<<1024, 256>>>((float4*)out);

    cudaFuncSetAttribute(gemm_kernel,
                         cudaFuncAttributeMaxDynamicSharedMemorySize,
                         GEMM_SMEM_BYTES);
    dim3 gg((N_NODES + BM - 1) / BM, N_REL);
    gemm_kernel<<<gg, 256, GEMM_SMEM_BYTES>>>(x, W);

    attn_kernel<<<1184, 256>>>(ei, et);
    softmax_kernel<<<592, 256>>>(et);
    scatter_kernel<<<1184, 256>>>(ei, et, out);
}